// round 9
// baseline (speedup 1.0000x reference)
#include <cuda_runtime.h>
#include <cstdint>
#include <cstddef>

typedef unsigned long long u64;

// ---- packed f32x2 helpers (Blackwell sm_103a) ----
#define FMA2(d, a, b, c) asm("fma.rn.f32x2 %0, %1, %2, %3;" : "=l"(d) : "l"(a), "l"(b), "l"(c))
#define MUL2(d, a, b)    asm("mul.rn.f32x2 %0, %1, %2;"     : "=l"(d) : "l"(a), "l"(b))
#define ADD2(d, a, b)    asm("add.rn.f32x2 %0, %1, %2;"     : "=l"(d) : "l"(a), "l"(b))

__device__ __forceinline__ u64 pack2(float lo, float hi) {
    u64 r; asm("mov.b64 %0, {%1, %2};" : "=l"(r) : "f"(lo), "f"(hi)); return r;
}
__device__ __forceinline__ float2 unpack2(u64 v) {
    float2 r; asm("mov.b64 {%0, %1}, %2;" : "=f"(r.x), "=f"(r.y) : "l"(v)); return r;
}
__device__ __forceinline__ void stg_cs_v4(float* p, float4 v) {
    asm volatile("st.global.cs.v4.f32 [%0], {%1, %2, %3, %4};"
                 :: "l"(p), "f"(v.x), "f"(v.y), "f"(v.z), "f"(v.w) : "memory");
}
__device__ __forceinline__ uint32_t smem_u32(const void* p) {
    uint32_t a;
    asm("{ .reg .u64 t; cvta.to.shared.u64 t, %1; cvt.u32.u64 %0, t; }" : "=r"(a) : "l"(p));
    return a;
}
__device__ __forceinline__ void mbar_init(uint32_t mbar, uint32_t cnt) {
    asm volatile("mbarrier.init.shared.b64 [%0], %1;" :: "r"(mbar), "r"(cnt) : "memory");
}
__device__ __forceinline__ void mbar_arrive(uint32_t mbar) {
    asm volatile("mbarrier.arrive.shared.b64 _, [%0];" :: "r"(mbar) : "memory");
}
__device__ __forceinline__ void mbar_expect_tx(uint32_t mbar, uint32_t bytes) {
    asm volatile("mbarrier.arrive.expect_tx.shared.b64 _, [%0], %1;" :: "r"(mbar), "r"(bytes) : "memory");
}
__device__ __forceinline__ void bulk_g2s(uint32_t dst, const void* src, uint32_t bytes, uint32_t mbar) {
    asm volatile("cp.async.bulk.shared::cta.global.mbarrier::complete_tx::bytes [%0], [%1], %2, [%3];"
                 :: "r"(dst), "l"(src), "r"(bytes), "r"(mbar) : "memory");
}
__device__ __forceinline__ void mbar_wait(uint32_t mbar, uint32_t parity) {
    asm volatile(
        "{\n\t"
        ".reg .pred P1;\n\t"
        "WL_%=:\n\t"
        "mbarrier.try_wait.parity.acquire.cta.shared::cta.b64 P1, [%0], %1, 0x989680;\n\t"
        "@P1 bra.uni WD_%=;\n\t"
        "bra.uni WL_%=;\n\t"
        "WD_%=:\n\t"
        "}"
        :: "r"(mbar), "r"(parity) : "memory");
}

constexpr int E_DIM = 1024;

// ============================================================================
// Fused: h = x@w1^T + b1 ; q = Pauli-Z cosine strings ; out = q@w2^T + b2
//   q0=c0, q1=c1, q2=c0c2, q3=c1c3, q4=c0c2c4, q5=c1c3c5, q6=c0c2c4c6,
//   q7=c0..c7  with c_i = cos(h_i)
//
// [A] TMA 2-slot ring; WARPS FREE-RUN: no per-stage __syncthreads. Each warp's
//     lane0 arrives on empty[slot] (count=8) after consuming; thread 0 alone
//     waits empty before refilling. Warps converge only at the epilogue sync.
// [B] q epilogue in smem. [C] out tail, w2 in regs, st.global.cs.
// ============================================================================
constexpr int RPB     = 64;                  // rows per block
constexpr int SROWS   = 4;                   // rows per pipeline stage
constexpr int NSLOT   = 2;                   // ring depth
constexpr int NSTAGE  = RPB / SROWS;         // 16
constexpr int STBYTES = SROWS * E_DIM * 4;   // 16384

__global__ void __launch_bounds__(256, 4)
ffq_fused(const float* __restrict__ x,  const float* __restrict__ w1,
          const float* __restrict__ b1, const float* __restrict__ w2,
          const float* __restrict__ b2, float* __restrict__ out, int rows)
{
    __shared__ __align__(128) float xs[NSLOT][SROWS * E_DIM];  // 32 KB ring
    __shared__ __align__(16) float s_part[RPB][8][8];          // 16 KB
    __shared__ __align__(16) float s_q[RPB][8];                // 2 KB
    __shared__ __align__(8) u64 mbar_full[NSLOT];
    __shared__ __align__(8) u64 mbar_empty[NSLOT];

    const int tid  = threadIdx.x;
    const int warp = tid >> 5;
    const int lane = tid & 31;

    const uint32_t mbF = smem_u32(&mbar_full[0]);
    const uint32_t mbE = smem_u32(&mbar_empty[0]);
    const uint32_t xs0 = smem_u32(&xs[0][0]);

    // ---- [A] phase-1 weights: f-pair packed, warp owns 128-wide e-slice ----
    const int e1 = warp * 128 + lane * 4;
    u64 wpk[4][4];
#pragma unroll
    for (int p = 0; p < 4; p++) {
        const float* w0 = w1 + (2 * p)     * E_DIM + e1;
        const float* w1r= w1 + (2 * p + 1) * E_DIM + e1;
#pragma unroll
        for (int e = 0; e < 4; e++)
            wpk[p][e] = pack2(w0[e], w1r[e]);
    }
    const float bf = b1[tid & 7];

    if (tid == 0) {
#pragma unroll
        for (int k = 0; k < NSLOT; k++) {
            mbar_init(mbF + k * 8, 1);   // flipped by TMA expect_tx+bytes
            mbar_init(mbE + k * 8, 8);   // flipped by 8 warp arrivals
        }
    }
    __syncthreads();

    const int    block_row0 = blockIdx.x * RPB;
    const float* src = x + (size_t)block_row0 * E_DIM;

    // prime both slots
    if (tid == 0) {
#pragma unroll
        for (int k = 0; k < NSLOT; k++) {
            mbar_expect_tx(mbF + k * 8, STBYTES);
            bulk_g2s(xs0 + k * STBYTES, src + (size_t)k * SROWS * E_DIM,
                     STBYTES, mbF + k * 8);
        }
    }

    const bool hi16 = (lane & 16);
    const bool hi8  = (lane & 8);

    for (int s = 0; s < NSTAGE; s++) {
        const int slot = s & (NSLOT - 1);
        const int ph   = (s >> 1) & 1;           // phase for NSLOT=2
        mbar_wait(mbF + slot * 8, ph);           // per-warp (no CTA barrier)

#pragma unroll
        for (int r = 0; r < SROWS; r++) {
            float4 xv = *reinterpret_cast<const float4*>(
                &xs[slot][r * E_DIM + e1]);
            u64 xd[4];
            xd[0] = pack2(xv.x, xv.x);
            xd[1] = pack2(xv.y, xv.y);
            xd[2] = pack2(xv.z, xv.z);
            xd[3] = pack2(xv.w, xv.w);

            u64 v0, v1, v2, v3;
            MUL2(v0, xd[0], wpk[0][0]);
            MUL2(v1, xd[0], wpk[1][0]);
            MUL2(v2, xd[0], wpk[2][0]);
            MUL2(v3, xd[0], wpk[3][0]);
#pragma unroll
            for (int e = 1; e < 4; e++) {
                FMA2(v0, xd[e], wpk[0][e], v0);
                FMA2(v1, xd[e], wpk[1][e], v1);
                FMA2(v2, xd[e], wpk[2][e], v2);
                FMA2(v3, xd[e], wpk[3][e], v3);
            }

            // packed value-halving butterfly on 4 u64 pair-accumulators
            {
                u64 s0 = hi16 ? v0 : v2;
                u64 s1 = hi16 ? v1 : v3;
                u64 k0 = hi16 ? v2 : v0;
                u64 k1 = hi16 ? v3 : v1;
                u64 r0 = __shfl_xor_sync(0xffffffffu, s0, 16);
                u64 r1 = __shfl_xor_sync(0xffffffffu, s1, 16);
                ADD2(v0, k0, r0);
                ADD2(v1, k1, r1);
            }
            u64 w;
            {
                u64 sv = hi8 ? v0 : v1;
                u64 kv = hi8 ? v1 : v0;
                u64 rv = __shfl_xor_sync(0xffffffffu, sv, 8);
                ADD2(w, kv, rv);
            }
            {
                u64 rv = __shfl_xor_sync(0xffffffffu, w, 4);
                ADD2(w, w, rv);
                rv = __shfl_xor_sync(0xffffffffu, w, 2);
                ADD2(w, w, rv);
                rv = __shfl_xor_sync(0xffffffffu, w, 1);
                ADD2(w, w, rv);
            }
            if ((lane & 7) == 0) {
                const int p = lane >> 3;
                *reinterpret_cast<u64*>(&s_part[s * SROWS + r][warp][2 * p]) = w;
            }
        }

        // this warp is done with the slot
        if (lane == 0)
            mbar_arrive(mbE + slot * 8);

        // thread 0: wait all 8 warps consumed, then refill for stage s+NSLOT
        if (tid == 0 && s + NSLOT < NSTAGE) {
            mbar_wait(mbE + slot * 8, ph);
            mbar_expect_tx(mbF + slot * 8, STBYTES);
            bulk_g2s(xs0 + slot * STBYTES,
                     src + (size_t)(s + NSLOT) * SROWS * E_DIM,
                     STBYTES, mbF + slot * 8);
        }
    }
    __syncthreads();   // converge: all s_part writes visible

    // ---- [B] q epilogue: 64 rows x 8 f = 512 items, 2 per thread ----
#pragma unroll
    for (int it = 0; it < 2; it++) {
        const int item = it * 256 + tid;
        const int r  = item >> 3;
        const int ff = item & 7;          // == tid & 7, matches bf

        float h = bf;
#pragma unroll
        for (int w = 0; w < 8; w++) h += s_part[r][w][ff];
        float c = __cosf(h);

        const int base = lane & 24;
        float cs[8];
#pragma unroll
        for (int jj = 0; jj < 8; jj++)
            cs[jj] = __shfl_sync(0xffffffffu, c, base + jj);

        float q;
        if (ff == 7) {
            q = cs[0]*cs[1]*cs[2]*cs[3]*cs[4]*cs[5]*cs[6]*cs[7];
        } else {
            q = 1.0f;
#pragma unroll
            for (int jj = 0; jj < 8; jj++)
                if (jj <= ff && ((jj ^ ff) & 1) == 0) q *= cs[jj];
        }
        s_q[r][ff] = q;
    }
    __syncthreads();

    // ---- [C] out tail: w2 f-pairs in regs (loaded after w1 regs die) ----
    const int e2 = tid * 4;
    u64 wp[4][4];
#pragma unroll
    for (int i = 0; i < 4; i++) {
        ulonglong2 v0 = *reinterpret_cast<const ulonglong2*>(w2 + (e2 + i) * 8);
        ulonglong2 v1 = *reinterpret_cast<const ulonglong2*>(w2 + (e2 + i) * 8 + 4);
        wp[i][0] = v0.x; wp[i][1] = v0.y;
        wp[i][2] = v1.x; wp[i][3] = v1.y;
    }
    u64 binit[4];
    {
        float4 bv = *reinterpret_cast<const float4*>(b2 + e2);
        binit[0] = pack2(bv.x, 0.f);
        binit[1] = pack2(bv.y, 0.f);
        binit[2] = pack2(bv.z, 0.f);
        binit[3] = pack2(bv.w, 0.f);
    }

    float* orow = out + (size_t)block_row0 * E_DIM + e2;
#pragma unroll 8
    for (int r = 0; r < RPB; r++) {
        ulonglong2 qv0 = *reinterpret_cast<const ulonglong2*>(&s_q[r][0]);
        ulonglong2 qv1 = *reinterpret_cast<const ulonglong2*>(&s_q[r][4]);

        float o[4];
#pragma unroll
        for (int i = 0; i < 4; i++) {
            u64 acc = binit[i];
            FMA2(acc, qv0.x, wp[i][0], acc);
            FMA2(acc, qv0.y, wp[i][1], acc);
            FMA2(acc, qv1.x, wp[i][2], acc);
            FMA2(acc, qv1.y, wp[i][3], acc);
            float2 t = unpack2(acc);
            o[i] = t.x + t.y;
        }
        stg_cs_v4(orow, make_float4(o[0], o[1], o[2], o[3]));
        orow += E_DIM;
    }
}

extern "C" void kernel_launch(void* const* d_in, const int* in_sizes, int n_in,
                              void* d_out, int out_size) {
    const float* x  = (const float*)d_in[0];
    const float* w1 = (const float*)d_in[1];
    const float* b1 = (const float*)d_in[2];
    const float* w2 = (const float*)d_in[3];
    const float* b2 = (const float*)d_in[4];
    float* out = (float*)d_out;

    const int rows = in_sizes[0] / E_DIM;        // 32768
    ffq_fused<<<rows / RPB, 256>>>(x, w1, b1, w2, b2, out, rows);  // 512 blocks
}

// round 10
// speedup vs baseline: 1.8682x; 1.8682x over previous
#include <cuda_runtime.h>
#include <cstdint>
#include <cstddef>

typedef unsigned long long u64;

// ---- packed f32x2 helpers (Blackwell sm_103a) ----
#define FMA2(d, a, b, c) asm("fma.rn.f32x2 %0, %1, %2, %3;" : "=l"(d) : "l"(a), "l"(b), "l"(c))
#define MUL2(d, a, b)    asm("mul.rn.f32x2 %0, %1, %2;"     : "=l"(d) : "l"(a), "l"(b))
#define ADD2(d, a, b)    asm("add.rn.f32x2 %0, %1, %2;"     : "=l"(d) : "l"(a), "l"(b))

__device__ __forceinline__ u64 pack2(float lo, float hi) {
    u64 r; asm("mov.b64 %0, {%1, %2};" : "=l"(r) : "f"(lo), "f"(hi)); return r;
}
__device__ __forceinline__ float2 unpack2(u64 v) {
    float2 r; asm("mov.b64 {%0, %1}, %2;" : "=f"(r.x), "=f"(r.y) : "l"(v)); return r;
}
// volatile LDGs: pin weight reloads inside the subtile loop (no ptxas hoist)
__device__ __forceinline__ float4 ldg_v4(const float* p) {
    float4 v;
    asm volatile("ld.global.nc.v4.f32 {%0, %1, %2, %3}, [%4];"
                 : "=f"(v.x), "=f"(v.y), "=f"(v.z), "=f"(v.w) : "l"(p));
    return v;
}
__device__ __forceinline__ ulonglong2 ldg_v2u64(const float* p) {
    ulonglong2 v;
    asm volatile("ld.global.nc.v2.b64 {%0, %1}, [%2];"
                 : "=l"(v.x), "=l"(v.y) : "l"(p));
    return v;
}
__device__ __forceinline__ void stg_cs_v4(float* p, float4 v) {
    asm volatile("st.global.cs.v4.f32 [%0], {%1, %2, %3, %4};"
                 :: "l"(p), "f"(v.x), "f"(v.y), "f"(v.z), "f"(v.w) : "memory");
}
__device__ __forceinline__ uint32_t smem_u32(const void* p) {
    uint32_t a;
    asm("{ .reg .u64 t; cvta.to.shared.u64 t, %1; cvt.u32.u64 %0, t; }" : "=r"(a) : "l"(p));
    return a;
}
__device__ __forceinline__ void mbar_init(uint32_t mbar, uint32_t cnt) {
    asm volatile("mbarrier.init.shared.b64 [%0], %1;" :: "r"(mbar), "r"(cnt) : "memory");
}
__device__ __forceinline__ void mbar_expect_tx(uint32_t mbar, uint32_t bytes) {
    asm volatile("mbarrier.arrive.expect_tx.shared.b64 _, [%0], %1;" :: "r"(mbar), "r"(bytes) : "memory");
}
__device__ __forceinline__ void bulk_g2s(uint32_t dst, const void* src, uint32_t bytes, uint32_t mbar) {
    asm volatile("cp.async.bulk.shared::cta.global.mbarrier::complete_tx::bytes [%0], [%1], %2, [%3];"
                 :: "r"(dst), "l"(src), "r"(bytes), "r"(mbar) : "memory");
}
__device__ __forceinline__ void mbar_wait(uint32_t mbar, uint32_t parity) {
    asm volatile(
        "{\n\t"
        ".reg .pred P1;\n\t"
        "WL_%=:\n\t"
        "mbarrier.try_wait.parity.acquire.cta.shared::cta.b64 P1, [%0], %1, 0x989680;\n\t"
        "@P1 bra.uni WD_%=;\n\t"
        "bra.uni WL_%=;\n\t"
        "WD_%=:\n\t"
        "}"
        :: "r"(mbar), "r"(parity) : "memory");
}

constexpr int E_DIM = 1024;

// ============================================================================
// Fused: h = x@w1^T + b1 ; q = Pauli-Z cosine strings ; out = q@w2^T + b2
//   q0=c0, q1=c1, q2=c0c2, q3=c1c3, q4=c0c2c4, q5=c1c3c5, q6=c0c2c4c6,
//   q7=c0..c7  with c_i = cos(h_i)
//
// R8 structure (TMA 2-slot ring, per-stage __syncthreads, packed butterfly,
// deferred q) + SUBTILE INTERLEAVING: [B]+[C] run per 32-row subtile, so the
// refills issued at stages 6-7 (for stages 8-9) stream DURING subtile 0's
// write-out — the CTA's read stream never idles through the write window.
// Weight regs (w1 pairs / w2 pairs) are reloaded per subtile via volatile LDG
// so their live ranges don't overlap (keeps regs <= 64, 4 CTAs/SM).
// ============================================================================
constexpr int RPB      = 64;                 // rows per block
constexpr int SUB      = 32;                 // rows per subtile
constexpr int SROWS    = 4;                  // rows per pipeline stage
constexpr int NSLOT    = 2;                  // ring depth
constexpr int NSTAGE   = RPB / SROWS;        // 16
constexpr int SUBSTAGE = SUB / SROWS;        // 8
constexpr int STBYTES  = SROWS * E_DIM * 4;  // 16384

__global__ void __launch_bounds__(256, 4)
ffq_fused(const float* __restrict__ x,  const float* __restrict__ w1,
          const float* __restrict__ b1, const float* __restrict__ w2,
          const float* __restrict__ b2, float* __restrict__ out, int rows)
{
    __shared__ __align__(128) float xs[NSLOT][SROWS * E_DIM];  // 32 KB ring
    __shared__ __align__(16) float s_part[SUB][8][8];          // 8 KB
    __shared__ __align__(16) float s_q[SUB][8];                // 1 KB
    __shared__ __align__(8) u64 mbar_s[NSLOT];

    const int tid  = threadIdx.x;
    const int warp = tid >> 5;
    const int lane = tid & 31;

    const uint32_t mb0 = smem_u32(&mbar_s[0]);
    const uint32_t xs0 = smem_u32(&xs[0][0]);

    const int e1 = warp * 128 + lane * 4;    // phase-1 e-slice
    const int e2 = tid * 4;                  // phase-2 out columns
    const float bf = b1[tid & 7];

    if (tid == 0) {
#pragma unroll
        for (int k = 0; k < NSLOT; k++) mbar_init(mb0 + k * 8, 1);
    }
    __syncthreads();

    const int    block_row0 = blockIdx.x * RPB;
    const float* src = x + (size_t)block_row0 * E_DIM;

    // prime the ring
    if (tid == 0) {
#pragma unroll
        for (int k = 0; k < NSLOT; k++) {
            mbar_expect_tx(mb0 + k * 8, STBYTES);
            bulk_g2s(xs0 + k * STBYTES, src + (size_t)k * SROWS * E_DIM,
                     STBYTES, mb0 + k * 8);
        }
    }

    const bool hi16 = (lane & 16);
    const bool hi8  = (lane & 8);

    for (int half = 0; half < 2; half++) {
        // ---- [A] w1 f-pair weights (reloaded per subtile; volatile LDG) ----
        u64 wpk[4][4];
#pragma unroll
        for (int p = 0; p < 4; p++) {
            float4 a = ldg_v4(w1 + (2 * p)     * E_DIM + e1);
            float4 b = ldg_v4(w1 + (2 * p + 1) * E_DIM + e1);
            wpk[p][0] = pack2(a.x, b.x);
            wpk[p][1] = pack2(a.y, b.y);
            wpk[p][2] = pack2(a.z, b.z);
            wpk[p][3] = pack2(a.w, b.w);
        }

        // ---- [A] stages for this subtile ----
        for (int ss = 0; ss < SUBSTAGE; ss++) {
            const int s    = half * SUBSTAGE + ss;
            const int slot = s & (NSLOT - 1);
            mbar_wait(mb0 + slot * 8, (s >> 1) & 1);

#pragma unroll
            for (int r = 0; r < SROWS; r++) {
                float4 xv = *reinterpret_cast<const float4*>(
                    &xs[slot][r * E_DIM + e1]);
                u64 xd[4];
                xd[0] = pack2(xv.x, xv.x);
                xd[1] = pack2(xv.y, xv.y);
                xd[2] = pack2(xv.z, xv.z);
                xd[3] = pack2(xv.w, xv.w);

                u64 v0, v1, v2, v3;
                MUL2(v0, xd[0], wpk[0][0]);
                MUL2(v1, xd[0], wpk[1][0]);
                MUL2(v2, xd[0], wpk[2][0]);
                MUL2(v3, xd[0], wpk[3][0]);
#pragma unroll
                for (int e = 1; e < 4; e++) {
                    FMA2(v0, xd[e], wpk[0][e], v0);
                    FMA2(v1, xd[e], wpk[1][e], v1);
                    FMA2(v2, xd[e], wpk[2][e], v2);
                    FMA2(v3, xd[e], wpk[3][e], v3);
                }

                // packed value-halving butterfly
                {
                    u64 s0 = hi16 ? v0 : v2;
                    u64 s1 = hi16 ? v1 : v3;
                    u64 k0 = hi16 ? v2 : v0;
                    u64 k1 = hi16 ? v3 : v1;
                    u64 r0 = __shfl_xor_sync(0xffffffffu, s0, 16);
                    u64 r1 = __shfl_xor_sync(0xffffffffu, s1, 16);
                    ADD2(v0, k0, r0);
                    ADD2(v1, k1, r1);
                }
                u64 w;
                {
                    u64 sv = hi8 ? v0 : v1;
                    u64 kv = hi8 ? v1 : v0;
                    u64 rv = __shfl_xor_sync(0xffffffffu, sv, 8);
                    ADD2(w, kv, rv);
                }
                {
                    u64 rv = __shfl_xor_sync(0xffffffffu, w, 4);
                    ADD2(w, w, rv);
                    rv = __shfl_xor_sync(0xffffffffu, w, 2);
                    ADD2(w, w, rv);
                    rv = __shfl_xor_sync(0xffffffffu, w, 1);
                    ADD2(w, w, rv);
                }
                if ((lane & 7) == 0) {
                    const int p = lane >> 3;
                    *reinterpret_cast<u64*>(
                        &s_part[ss * SROWS + r][warp][2 * p]) = w;
                }
            }
            __syncthreads();   // slot drained; s_part rows committed

            if (tid == 0 && s + NSLOT < NSTAGE) {
                mbar_expect_tx(mb0 + slot * 8, STBYTES);
                bulk_g2s(xs0 + slot * STBYTES,
                         src + (size_t)(s + NSLOT) * SROWS * E_DIM,
                         STBYTES, mb0 + slot * 8);
            }
        }

        // ---- [B] q for this subtile: 32 rows x 8 f = 256 items ----
        {
            const int r  = tid >> 3;          // 0..31
            const int ff = tid & 7;           // matches bf

            float h = bf;
#pragma unroll
            for (int w = 0; w < 8; w++) h += s_part[r][w][ff];
            float c = __cosf(h);

            const int base = lane & 24;
            float cs[8];
#pragma unroll
            for (int jj = 0; jj < 8; jj++)
                cs[jj] = __shfl_sync(0xffffffffu, c, base + jj);

            float q;
            if (ff == 7) {
                q = cs[0]*cs[1]*cs[2]*cs[3]*cs[4]*cs[5]*cs[6]*cs[7];
            } else {
                q = 1.0f;
#pragma unroll
                for (int jj = 0; jj < 8; jj++)
                    if (jj <= ff && ((jj ^ ff) & 1) == 0) q *= cs[jj];
            }
            s_q[r][ff] = q;
        }
        __syncthreads();

        // ---- [C] out tail for this subtile (w2 reloaded; volatile LDG) ----
        {
            u64 wp[4][4];
#pragma unroll
            for (int i = 0; i < 4; i++) {
                ulonglong2 v0 = ldg_v2u64(w2 + (e2 + i) * 8);
                ulonglong2 v1 = ldg_v2u64(w2 + (e2 + i) * 8 + 4);
                wp[i][0] = v0.x; wp[i][1] = v0.y;
                wp[i][2] = v1.x; wp[i][3] = v1.y;
            }
            float4 bv = ldg_v4(b2 + e2);
            u64 binit[4];
            binit[0] = pack2(bv.x, 0.f);
            binit[1] = pack2(bv.y, 0.f);
            binit[2] = pack2(bv.z, 0.f);
            binit[3] = pack2(bv.w, 0.f);

            float* orow = out + (size_t)(block_row0 + half * SUB) * E_DIM + e2;
#pragma unroll 8
            for (int r = 0; r < SUB; r++) {
                ulonglong2 qv0 = *reinterpret_cast<const ulonglong2*>(&s_q[r][0]);
                ulonglong2 qv1 = *reinterpret_cast<const ulonglong2*>(&s_q[r][4]);

                float o[4];
#pragma unroll
                for (int i = 0; i < 4; i++) {
                    u64 acc = binit[i];
                    FMA2(acc, qv0.x, wp[i][0], acc);
                    FMA2(acc, qv0.y, wp[i][1], acc);
                    FMA2(acc, qv1.x, wp[i][2], acc);
                    FMA2(acc, qv1.y, wp[i][3], acc);
                    float2 t = unpack2(acc);
                    o[i] = t.x + t.y;
                }
                stg_cs_v4(orow, make_float4(o[0], o[1], o[2], o[3]));
                orow += E_DIM;
            }
        }
        // no sync needed here: subtile1's s_part writes follow the post-[B]
        // sync, and s_q rewrite is fenced by subtile1's stage syncs.
    }
}

extern "C" void kernel_launch(void* const* d_in, const int* in_sizes, int n_in,
                              void* d_out, int out_size) {
    const float* x  = (const float*)d_in[0];
    const float* w1 = (const float*)d_in[1];
    const float* b1 = (const float*)d_in[2];
    const float* w2 = (const float*)d_in[3];
    const float* b2 = (const float*)d_in[4];
    float* out = (float*)d_out;

    const int rows = in_sizes[0] / E_DIM;        // 32768
    ffq_fused<<<rows / RPB, 256>>>(x, w1, b1, w2, b2, out, rows);  // 512 blocks
}

// round 11
// speedup vs baseline: 2.2123x; 1.1842x over previous
#include <cuda_runtime.h>
#include <cstdint>
#include <cstddef>

typedef unsigned long long u64;

// ---- packed f32x2 helpers (Blackwell sm_103a) ----
#define FMA2(d, a, b, c) asm("fma.rn.f32x2 %0, %1, %2, %3;" : "=l"(d) : "l"(a), "l"(b), "l"(c))
#define MUL2(d, a, b)    asm("mul.rn.f32x2 %0, %1, %2;"     : "=l"(d) : "l"(a), "l"(b))
#define ADD2(d, a, b)    asm("add.rn.f32x2 %0, %1, %2;"     : "=l"(d) : "l"(a), "l"(b))

__device__ __forceinline__ u64 pack2(float lo, float hi) {
    u64 r; asm("mov.b64 %0, {%1, %2};" : "=l"(r) : "f"(lo), "f"(hi)); return r;
}
__device__ __forceinline__ float2 unpack2(u64 v) {
    float2 r; asm("mov.b64 {%0, %1}, %2;" : "=f"(r.x), "=f"(r.y) : "l"(v)); return r;
}
__device__ __forceinline__ void stg_cs_v4(float* p, float4 v) {
    asm volatile("st.global.cs.v4.f32 [%0], {%1, %2, %3, %4};"
                 :: "l"(p), "f"(v.x), "f"(v.y), "f"(v.z), "f"(v.w) : "memory");
}
__device__ __forceinline__ uint32_t smem_u32(const void* p) {
    uint32_t a;
    asm("{ .reg .u64 t; cvta.to.shared.u64 t, %1; cvt.u32.u64 %0, t; }" : "=r"(a) : "l"(p));
    return a;
}
__device__ __forceinline__ void mbar_init(uint32_t mbar, uint32_t cnt) {
    asm volatile("mbarrier.init.shared.b64 [%0], %1;" :: "r"(mbar), "r"(cnt) : "memory");
}
__device__ __forceinline__ void mbar_expect_tx(uint32_t mbar, uint32_t bytes) {
    asm volatile("mbarrier.arrive.expect_tx.shared.b64 _, [%0], %1;" :: "r"(mbar), "r"(bytes) : "memory");
}
__device__ __forceinline__ void bulk_g2s(uint32_t dst, const void* src, uint32_t bytes, uint32_t mbar) {
    asm volatile("cp.async.bulk.shared::cta.global.mbarrier::complete_tx::bytes [%0], [%1], %2, [%3];"
                 :: "r"(dst), "l"(src), "r"(bytes), "r"(mbar) : "memory");
}
__device__ __forceinline__ void mbar_wait(uint32_t mbar, uint32_t parity) {
    asm volatile(
        "{\n\t"
        ".reg .pred P1;\n\t"
        "WL_%=:\n\t"
        "mbarrier.try_wait.parity.acquire.cta.shared::cta.b64 P1, [%0], %1, 0x989680;\n\t"
        "@P1 bra.uni WD_%=;\n\t"
        "bra.uni WL_%=;\n\t"
        "WD_%=:\n\t"
        "}"
        :: "r"(mbar), "r"(parity) : "memory");
}

constexpr int E_DIM = 1024;

// ============================================================================
// Fused: h = x@w1^T + b1 ; q = Pauli-Z cosine strings ; out = q@w2^T + b2
//   q0=c0, q1=c1, q2=c0c2, q3=c1c3, q4=c0c2c4, q5=c1c3c5, q6=c0c2c4c6,
//   q7=c0..c7  with c_i = cos(h_i)
//
// R8 structure verbatim (TMA 2-slot ring, per-stage __syncthreads, packed
// f-pair butterfly, deferred q, w2-in-regs tail) with RPB 64 -> 32:
// grid 1024 instead of 512 removes the 1-wave CTA quantization imbalance
// (512 blocks = 68 SMs x4 + 80 SMs x3 -> makespan set by the 4-CTA SMs).
// ============================================================================
constexpr int RPB     = 32;                  // rows per block
constexpr int SROWS   = 4;                   // rows per pipeline stage
constexpr int NSLOT   = 2;                   // ring depth
constexpr int NSTAGE  = RPB / SROWS;         // 8
constexpr int STBYTES = SROWS * E_DIM * 4;   // 16384

__global__ void __launch_bounds__(256, 4)
ffq_fused(const float* __restrict__ x,  const float* __restrict__ w1,
          const float* __restrict__ b1, const float* __restrict__ w2,
          const float* __restrict__ b2, float* __restrict__ out, int rows)
{
    __shared__ __align__(128) float xs[NSLOT][SROWS * E_DIM];  // 32 KB ring
    __shared__ __align__(16) float s_part[RPB][8][8];          // 8 KB
    __shared__ __align__(16) float s_q[RPB][8];                // 1 KB
    __shared__ __align__(8) u64 mbar_s[NSLOT];

    const int tid  = threadIdx.x;
    const int warp = tid >> 5;
    const int lane = tid & 31;

    const uint32_t mb0 = smem_u32(&mbar_s[0]);
    const uint32_t xs0 = smem_u32(&xs[0][0]);

    // ---- [A] phase-1 weights: f-pair packed, warp owns 128-wide e-slice ----
    const int e1 = warp * 128 + lane * 4;
    u64 wpk[4][4];
#pragma unroll
    for (int p = 0; p < 4; p++) {
        const float* w0 = w1 + (2 * p)     * E_DIM + e1;
        const float* w1r= w1 + (2 * p + 1) * E_DIM + e1;
#pragma unroll
        for (int e = 0; e < 4; e++)
            wpk[p][e] = pack2(w0[e], w1r[e]);
    }
    const float bf = b1[tid & 7];

    if (tid == 0) {
#pragma unroll
        for (int k = 0; k < NSLOT; k++) mbar_init(mb0 + k * 8, 1);
    }
    __syncthreads();

    const int    block_row0 = blockIdx.x * RPB;
    const float* src = x + (size_t)block_row0 * E_DIM;

    if (tid == 0) {
#pragma unroll
        for (int k = 0; k < NSLOT; k++) {
            mbar_expect_tx(mb0 + k * 8, STBYTES);
            bulk_g2s(xs0 + k * STBYTES, src + (size_t)k * SROWS * E_DIM,
                     STBYTES, mb0 + k * 8);
        }
    }

    const bool hi16 = (lane & 16);
    const bool hi8  = (lane & 8);

    for (int s = 0; s < NSTAGE; s++) {
        const int slot = s & (NSLOT - 1);
        mbar_wait(mb0 + slot * 8, (s >> 1) & 1);

#pragma unroll
        for (int r = 0; r < SROWS; r++) {
            float4 xv = *reinterpret_cast<const float4*>(
                &xs[slot][r * E_DIM + e1]);
            u64 xd[4];
            xd[0] = pack2(xv.x, xv.x);
            xd[1] = pack2(xv.y, xv.y);
            xd[2] = pack2(xv.z, xv.z);
            xd[3] = pack2(xv.w, xv.w);

            u64 v0, v1, v2, v3;
            MUL2(v0, xd[0], wpk[0][0]);
            MUL2(v1, xd[0], wpk[1][0]);
            MUL2(v2, xd[0], wpk[2][0]);
            MUL2(v3, xd[0], wpk[3][0]);
#pragma unroll
            for (int e = 1; e < 4; e++) {
                FMA2(v0, xd[e], wpk[0][e], v0);
                FMA2(v1, xd[e], wpk[1][e], v1);
                FMA2(v2, xd[e], wpk[2][e], v2);
                FMA2(v3, xd[e], wpk[3][e], v3);
            }

            // packed value-halving butterfly on 4 u64 pair-accumulators
            {
                u64 s0 = hi16 ? v0 : v2;
                u64 s1 = hi16 ? v1 : v3;
                u64 k0 = hi16 ? v2 : v0;
                u64 k1 = hi16 ? v3 : v1;
                u64 r0 = __shfl_xor_sync(0xffffffffu, s0, 16);
                u64 r1 = __shfl_xor_sync(0xffffffffu, s1, 16);
                ADD2(v0, k0, r0);
                ADD2(v1, k1, r1);
            }
            u64 w;
            {
                u64 sv = hi8 ? v0 : v1;
                u64 kv = hi8 ? v1 : v0;
                u64 rv = __shfl_xor_sync(0xffffffffu, sv, 8);
                ADD2(w, kv, rv);
            }
            {
                u64 rv = __shfl_xor_sync(0xffffffffu, w, 4);
                ADD2(w, w, rv);
                rv = __shfl_xor_sync(0xffffffffu, w, 2);
                ADD2(w, w, rv);
                rv = __shfl_xor_sync(0xffffffffu, w, 1);
                ADD2(w, w, rv);
            }
            if ((lane & 7) == 0) {
                const int p = lane >> 3;
                *reinterpret_cast<u64*>(&s_part[s * SROWS + r][warp][2 * p]) = w;
            }
        }
        __syncthreads();   // slot drained; s_part row-group committed

        if (tid == 0 && s + NSLOT < NSTAGE) {
            mbar_expect_tx(mb0 + slot * 8, STBYTES);
            bulk_g2s(xs0 + slot * STBYTES,
                     src + (size_t)(s + NSLOT) * SROWS * E_DIM,
                     STBYTES, mb0 + slot * 8);
        }
    }

    // ---- [B] q epilogue: 32 rows x 8 f = 256 items, 1 per thread ----
    {
        const int r  = tid >> 3;          // 0..31
        const int ff = tid & 7;           // matches bf

        float h = bf;
#pragma unroll
        for (int w = 0; w < 8; w++) h += s_part[r][w][ff];
        float c = __cosf(h);

        const int base = lane & 24;
        float cs[8];
#pragma unroll
        for (int jj = 0; jj < 8; jj++)
            cs[jj] = __shfl_sync(0xffffffffu, c, base + jj);

        float q;
        if (ff == 7) {
            q = cs[0]*cs[1]*cs[2]*cs[3]*cs[4]*cs[5]*cs[6]*cs[7];
        } else {
            q = 1.0f;
#pragma unroll
            for (int jj = 0; jj < 8; jj++)
                if (jj <= ff && ((jj ^ ff) & 1) == 0) q *= cs[jj];
        }
        s_q[r][ff] = q;
    }
    __syncthreads();

    // ---- [C] out tail: w2 f-pairs in regs (loaded after w1 regs die) ----
    const int e2 = tid * 4;
    u64 wp[4][4];
#pragma unroll
    for (int i = 0; i < 4; i++) {
        ulonglong2 v0 = *reinterpret_cast<const ulonglong2*>(w2 + (e2 + i) * 8);
        ulonglong2 v1 = *reinterpret_cast<const ulonglong2*>(w2 + (e2 + i) * 8 + 4);
        wp[i][0] = v0.x; wp[i][1] = v0.y;
        wp[i][2] = v1.x; wp[i][3] = v1.y;
    }
    u64 binit[4];
    {
        float4 bv = *reinterpret_cast<const float4*>(b2 + e2);
        binit[0] = pack2(bv.x, 0.f);
        binit[1] = pack2(bv.y, 0.f);
        binit[2] = pack2(bv.z, 0.f);
        binit[3] = pack2(bv.w, 0.f);
    }

    float* orow = out + (size_t)block_row0 * E_DIM + e2;
#pragma unroll 8
    for (int r = 0; r < RPB; r++) {
        ulonglong2 qv0 = *reinterpret_cast<const ulonglong2*>(&s_q[r][0]);
        ulonglong2 qv1 = *reinterpret_cast<const ulonglong2*>(&s_q[r][4]);

        float o[4];
#pragma unroll
        for (int i = 0; i < 4; i++) {
            u64 acc = binit[i];
            FMA2(acc, qv0.x, wp[i][0], acc);
            FMA2(acc, qv0.y, wp[i][1], acc);
            FMA2(acc, qv1.x, wp[i][2], acc);
            FMA2(acc, qv1.y, wp[i][3], acc);
            float2 t = unpack2(acc);
            o[i] = t.x + t.y;
        }
        stg_cs_v4(orow, make_float4(o[0], o[1], o[2], o[3]));
        orow += E_DIM;
    }
}

extern "C" void kernel_launch(void* const* d_in, const int* in_sizes, int n_in,
                              void* d_out, int out_size) {
    const float* x  = (const float*)d_in[0];
    const float* w1 = (const float*)d_in[1];
    const float* b1 = (const float*)d_in[2];
    const float* w2 = (const float*)d_in[3];
    const float* b2 = (const float*)d_in[4];
    float* out = (float*)d_out;

    const int rows = in_sizes[0] / E_DIM;        // 32768
    ffq_fused<<<rows / RPB, 256>>>(x, w1, b1, w2, b2, out, rows);  // 1024 blocks
}